// round 6
// baseline (speedup 1.0000x reference)
#include <cuda_runtime.h>
#include <cstdint>

// ============================================================
// VectorQuantizer on GB300 (baseline-PTX path):
//   int8 IMMA (m16n8k32) GEMM, per-token/per-code scales,
//   per-tile min2 -> contributor top-3 (48 cands/token),
//   threshold-gated exact fp32 rescore. Round 6.
// ============================================================

#define DDIM 256
#define MAXN 32768
#define MAXK 8192
#define DELTA 1.5f

__device__ char   g_z8[(size_t)MAXN * DDIM];      // int8 tokens (per-row scale)
__device__ char   g_c8[(size_t)MAXK * DDIM];      // int8 codebook (per-row scale)
__device__ float  g_zscale[MAXN];                 // z row scale (max/127)
__device__ float2 g_cns[MAXK];                    // {||c||^2 exact, c row scale}
__device__ unsigned long long g_cand48[(size_t)MAXN * 48];  // (fkey|idx)
__device__ float  g_part[MAXN];                   // per-token loss partial
__device__ double g_lpart[128];                   // loss stage-1 partials

// ---------------- PTX helpers ----------------
__device__ __forceinline__ uint32_t smem_u32(const void* p) {
    uint32_t a;
    asm("{ .reg .u64 t; cvta.to.shared.u64 t, %1; cvt.u32.u64 %0, t; }" : "=r"(a) : "l"(p));
    return a;
}
__device__ __forceinline__ void cp16(uint32_t s, const void* g) {
    asm volatile("cp.async.cg.shared.global [%0], [%1], 16;" :: "r"(s), "l"(g) : "memory");
}
__device__ __forceinline__ void cp_commit() {
    asm volatile("cp.async.commit_group;" ::: "memory");
}
template <int N> __device__ __forceinline__ void cp_wait() {
    asm volatile("cp.async.wait_group %0;" :: "n"(N) : "memory");
}
__device__ __forceinline__ void ldsm4(uint32_t a[4], uint32_t addr) {
    asm volatile("ldmatrix.sync.aligned.m8n8.x4.shared.b16 {%0,%1,%2,%3}, [%4];"
                 : "=r"(a[0]), "=r"(a[1]), "=r"(a[2]), "=r"(a[3]) : "r"(addr));
}
__device__ __forceinline__ void ldsm2(uint32_t b[2], uint32_t addr) {
    asm volatile("ldmatrix.sync.aligned.m8n8.x2.shared.b16 {%0,%1}, [%2];"
                 : "=r"(b[0]), "=r"(b[1]) : "r"(addr));
}
__device__ __forceinline__ void imma16832(int d[4], const uint32_t a[4],
                                          const uint32_t b[2]) {
    asm volatile(
        "mma.sync.aligned.m16n8k32.row.col.s32.s8.s8.s32 "
        "{%0,%1,%2,%3},{%4,%5,%6,%7},{%8,%9},{%0,%1,%2,%3};"
        : "+r"(d[0]), "+r"(d[1]), "+r"(d[2]), "+r"(d[3])
        : "r"(a[0]), "r"(a[1]), "r"(a[2]), "r"(a[3]), "r"(b[0]), "r"(b[1]));
}

__device__ __forceinline__ unsigned fkey(float f) {
    unsigned u = __float_as_uint(f);
    return (u & 0x80000000u) ? ~u : (u | 0x80000000u);
}
__device__ __forceinline__ float unfkey(unsigned k) {
    unsigned u = (k & 0x80000000u) ? (k ^ 0x80000000u) : ~k;
    return __uint_as_float(u);
}
// exact int->float for |x| < 2^22 (our dots: |d| <= 256*127*127 = 4129024 < 2^22)
__device__ __forceinline__ float i2f_fast(int x) {
    return __int_as_float(x + 0x4B400000) - 12582912.0f;
}

// ---------------- SMEM map for k_argmin ----------------
// [cns: 8192*float2 = 65536][A: 128 x 272 = 34816][B: 2 x 18432 = 36864]
#define AS 272
#define BS 144
#define CNS_OFF 0
#define A_OFF 65536
#define B_OFF 100352
#define B_BYTES 18432
#define SMEM_TOTAL 137216

// ---------------- prep: per-row max + quantize ----------------
__device__ __forceinline__ uint32_t q4(float4 v, float r) {
    int a = __float2int_rn(v.x * r), b = __float2int_rn(v.y * r);
    int c = __float2int_rn(v.z * r), d = __float2int_rn(v.w * r);
    a = max(-127, min(127, a)); b = max(-127, min(127, b));
    c = max(-127, min(127, c)); d = max(-127, min(127, d));
    return (uint32_t)(a & 0xff) | ((uint32_t)(b & 0xff) << 8) |
           ((uint32_t)(c & 0xff) << 16) | ((uint32_t)(d & 0xff) << 24);
}

__global__ void k_prep_z(const float* __restrict__ z, int N) {
    int t = blockIdx.x * (blockDim.x >> 5) + (threadIdx.x >> 5);
    int lane = threadIdx.x & 31;
    if (t >= N) return;
    float4 v0 = ((const float4*)z)[(size_t)t * 64 + lane];
    float4 v1 = ((const float4*)z)[(size_t)t * 64 + 32 + lane];
    float m = fmaxf(fmaxf(fmaxf(fabsf(v0.x), fabsf(v0.y)), fmaxf(fabsf(v0.z), fabsf(v0.w))),
                    fmaxf(fmaxf(fabsf(v1.x), fabsf(v1.y)), fmaxf(fabsf(v1.z), fabsf(v1.w))));
#pragma unroll
    for (int o = 16; o; o >>= 1) m = fmaxf(m, __shfl_xor_sync(0xffffffffu, m, o));
    float r = (m > 0.f) ? 127.f / m : 0.f;
    uint32_t* o8 = (uint32_t*)(g_z8 + (size_t)t * DDIM);
    o8[lane] = q4(v0, r);
    o8[32 + lane] = q4(v1, r);
    if (lane == 0) g_zscale[t] = m / 127.f;
}

__global__ void k_prep_c(const float* __restrict__ cb, int K) {
    int k = blockIdx.x * (blockDim.x >> 5) + (threadIdx.x >> 5);
    int lane = threadIdx.x & 31;
    if (k >= K) return;
    float4 v0 = ((const float4*)cb)[(size_t)k * 64 + lane];
    float4 v1 = ((const float4*)cb)[(size_t)k * 64 + 32 + lane];
    float s = v0.x * v0.x + v0.y * v0.y + v0.z * v0.z + v0.w * v0.w +
              v1.x * v1.x + v1.y * v1.y + v1.z * v1.z + v1.w * v1.w;
    float m = fmaxf(fmaxf(fmaxf(fabsf(v0.x), fabsf(v0.y)), fmaxf(fabsf(v0.z), fabsf(v0.w))),
                    fmaxf(fmaxf(fabsf(v1.x), fabsf(v1.y)), fmaxf(fabsf(v1.z), fabsf(v1.w))));
#pragma unroll
    for (int o = 16; o; o >>= 1) {
        s += __shfl_xor_sync(0xffffffffu, s, o);
        m = fmaxf(m, __shfl_xor_sync(0xffffffffu, m, o));
    }
    float r = (m > 0.f) ? 127.f / m : 0.f;
    uint32_t* o8 = (uint32_t*)(g_c8 + (size_t)k * DDIM);
    o8[lane] = q4(v0, r);
    o8[32 + lane] = q4(v1, r);
    if (lane == 0) g_cns[k] = make_float2(s, m / 127.f);
}

// ---------------- fused int8 GEMM + min2/top-3 candidates ----------------
__global__ void __launch_bounds__(256, 1) k_argmin(int ntiles) {
    extern __shared__ char smem[];
    uint32_t sb = smem_u32(smem);
    int tid = threadIdx.x;
    int lane = tid & 31, wid = tid >> 5;
    int wm = wid >> 2;          // M group (0..1)
    int wn = wid & 3;           // N group (0..3)
    int tx = lane & 3;
    long t0 = (long)blockIdx.x * 128;

    // ---- async prologue: cns table + A panel + B chunk 0 ----
#pragma unroll
    for (int it = 0; it < 16; it++) {           // cns: 4096 x 16B
        int f = tid + 256 * it;
        cp16(sb + CNS_OFF + f * 16, (const char*)g_cns + f * 16);
    }
#pragma unroll
    for (int it = 0; it < 8; it++) {            // A: 128 rows x 16 cp16
        int f = tid + 256 * it;
        int row = f >> 4, c = f & 15;
        cp16(sb + A_OFF + row * AS + c * 16,
             g_z8 + (t0 + row) * DDIM + c * 16);
    }
#pragma unroll
    for (int it = 0; it < 4; it++) {            // B chunk q=0
        int f = tid + 256 * it;
        int row = f >> 3, c = f & 7;
        cp16(sb + B_OFF + row * BS + c * 16,
             g_c8 + (size_t)row * DDIM + c * 16);
    }
    cp_commit();

    // per-slot token scale factor: -2 * sz(token)
    float szn[8];
#pragma unroll
    for (int mi = 0; mi < 4; mi++)
#pragma unroll
        for (int h = 0; h < 2; h++) {
            int token = wm * 64 + mi * 16 + h * 8 + (lane >> 2);
            szn[mi * 2 + h] = -2.f * __ldg(&g_zscale[t0 + token]);
        }

    // ---- state ----
    int d[4][4][4];
    float ts[8][3];
    int   ti[8][3];
#pragma unroll
    for (int s = 0; s < 8; s++)
#pragma unroll
        for (int e = 0; e < 3; e++) { ts[s][e] = 3.4e38f; ti[s][e] = 0; }

    int a_r  = (lane & 7) + ((lane >> 3) & 1) * 8;
    int a_kb = ((lane >> 4) & 1) * 16;
    int b_r  = lane & 7;
    int b_kb = ((lane >> 3) & 1) * 16;

    int Q = ntiles * 2;                          // 128-dim chunks
    for (int q = 0; q < Q; q++) {
        int buf = q & 1;
        if (q + 1 < Q) {
            int nq = q + 1;
            int nkt = nq >> 1, ndc = nq & 1;
            uint32_t bb = sb + B_OFF + (nq & 1) * B_BYTES;
#pragma unroll
            for (int it = 0; it < 4; it++) {
                int f = tid + 256 * it;
                int row = f >> 3, c = f & 7;
                cp16(bb + row * BS + c * 16,
                     g_c8 + ((size_t)(nkt * 128 + row)) * DDIM + ndc * 128 + c * 16);
            }
            cp_commit();
            cp_wait<1>();
        } else {
            cp_wait<0>();
        }
        __syncthreads();

        int kt = q >> 1, dc = q & 1;
        if (dc == 0) {
#pragma unroll
            for (int mi = 0; mi < 4; mi++)
#pragma unroll
                for (int ni = 0; ni < 4; ni++)
#pragma unroll
                    for (int r = 0; r < 4; r++) d[mi][ni][r] = 0;
        }
        uint32_t Bb = sb + B_OFF + buf * B_BYTES;

#pragma unroll
        for (int k0 = 0; k0 < 128; k0 += 32) {
            uint32_t a[4][4], bf[4][2];
#pragma unroll
            for (int mi = 0; mi < 4; mi++)
                ldsm4(a[mi], sb + A_OFF + (wm * 64 + mi * 16 + a_r) * AS +
                             dc * 128 + k0 + a_kb);
#pragma unroll
            for (int ni = 0; ni < 4; ni++)
                ldsm2(bf[ni], Bb + (wn * 32 + ni * 8 + b_r) * BS + k0 + b_kb);
#pragma unroll
            for (int mi = 0; mi < 4; mi++)
#pragma unroll
                for (int ni = 0; ni < 4; ni++)
                    imma16832(d[mi][ni], a[mi], bf[ni]);
        }

        if (dc == 1) {
            // ---- scoring: s = cn + (-2*sz)*(sc*dot); per-slot min2; top-3 ----
            int cbase = kt * 128 + wn * 32 + 2 * tx;
            float4 cns4[4];   // {cn0, sc0, cn1, sc1} for pair (c0, c0+1)
#pragma unroll
            for (int ni = 0; ni < 4; ni++)
                cns4[ni] = *(const float4*)(smem + CNS_OFF + (cbase + ni * 8) * 8);
#pragma unroll
            for (int mi = 0; mi < 4; mi++)
#pragma unroll
                for (int h = 0; h < 2; h++) {
                    int slot = mi * 2 + h;
                    float inv = szn[slot];
                    float m1 = 3.4e38f, m2 = 3.4e38f;
                    int i1 = 0, i2 = 0;
#pragma unroll
                    for (int ni = 0; ni < 4; ni++) {
                        int c0 = cbase + ni * 8;
                        float f0 = i2f_fast(d[mi][ni][h * 2 + 0]);
                        float f1 = i2f_fast(d[mi][ni][h * 2 + 1]);
                        float s0 = fmaf(inv * cns4[ni].y, f0, cns4[ni].x);
                        float s1 = fmaf(inv * cns4[ni].w, f1, cns4[ni].z);
                        // branchless min2 insert (s0)
                        {
                            bool p1 = s0 < m1, p2 = s0 < m2;
                            float m2n = p2 ? (p1 ? m1 : s0) : m2;
                            int   i2n = p2 ? (p1 ? i1 : c0) : i2;
                            m1 = p1 ? s0 : m1; i1 = p1 ? c0 : i1;
                            m2 = m2n; i2 = i2n;
                        }
                        {
                            int c1 = c0 + 1;
                            bool p1 = s1 < m1, p2 = s1 < m2;
                            float m2n = p2 ? (p1 ? m1 : s1) : m2;
                            int   i2n = p2 ? (p1 ? i1 : c1) : i2;
                            m1 = p1 ? s1 : m1; i1 = p1 ? c1 : i1;
                            m2 = m2n; i2 = i2n;
                        }
                    }
                    // insert tile (m1,i1),(m2,i2) into persistent top-3 (rare)
#pragma unroll
                    for (int e = 0; e < 2; e++) {
                        float v = e ? m2 : m1;
                        int   c = e ? i2 : i1;
                        if (v < ts[slot][2]) {
                            if (v < ts[slot][1]) {
                                ts[slot][2] = ts[slot][1]; ti[slot][2] = ti[slot][1];
                                if (v < ts[slot][0]) {
                                    ts[slot][1] = ts[slot][0]; ti[slot][1] = ti[slot][0];
                                    ts[slot][0] = v; ti[slot][0] = c;
                                } else { ts[slot][1] = v; ti[slot][1] = c; }
                            } else { ts[slot][2] = v; ti[slot][2] = c; }
                        }
                    }
                }
        }
        __syncthreads();
    }

    // ---- stage all 48 candidates per token to smem, then coalesced gmem ----
    unsigned long long* red = (unsigned long long*)smem;
    int contrib = wn * 4 + tx;
#pragma unroll
    for (int mi = 0; mi < 4; mi++)
#pragma unroll
        for (int h = 0; h < 2; h++) {
            int slot = mi * 2 + h;
            int token = wm * 64 + mi * 16 + h * 8 + (lane >> 2);
#pragma unroll
            for (int e = 0; e < 3; e++)
                red[token * 48 + contrib * 3 + e] =
                    (((unsigned long long)fkey(ts[slot][e])) << 32) |
                    (unsigned)ti[slot][e];
        }
    __syncthreads();

    unsigned long long* outc = g_cand48 + (size_t)t0 * 48;
    for (int idx = tid; idx < 128 * 48; idx += 256)
        outc[idx] = red[idx];
}

// ---------------- threshold-gated exact rescore + gather ----------------
__global__ void k_finish(const float* __restrict__ z, const float* __restrict__ cb,
                         float* __restrict__ out_zq, float* __restrict__ out_idx,
                         int has_idx, int N) {
    int warp = blockIdx.x * (blockDim.x >> 5) + (threadIdx.x >> 5);
    int lane = threadIdx.x & 31;
    if (warp >= N) return;
    long t = warp;
    const unsigned long long* c48 = g_cand48 + (size_t)t * 48;

    float4 xv0 = ((const float4*)z)[t * 64 + lane];
    float4 xv1 = ((const float4*)z)[t * 64 + 32 + lane];

    // min noisy score over 48 entries
    unsigned long long va = __ldg(&c48[lane]);
    unsigned long long vb = (lane < 16) ? __ldg(&c48[32 + lane]) : ~0ull;
    unsigned long long mn = min(va, vb);
#pragma unroll
    for (int o = 16; o; o >>= 1)
        mn = min(mn, __shfl_xor_sync(0xffffffffu, mn, o));
    float thr = unfkey((unsigned)(mn >> 32)) + DELTA;

    float best_s = 3.4e38f;
    int best_i = 0x7fffffff;
    for (int j = 0; j < 48; j++) {
        unsigned long long v = __ldg(&c48[j]);        // uniform -> broadcast
        float ns = unfkey((unsigned)(v >> 32));
        if (ns > thr) continue;
        int ci = (int)(v & 0xffffffffu);
        float4 c0 = __ldg(&((const float4*)cb)[(long)ci * 64 + lane]);
        float4 c1 = __ldg(&((const float4*)cb)[(long)ci * 64 + 32 + lane]);
        float dx, s = 0.f;
        dx = xv0.x - c0.x; s += dx * dx;  dx = xv0.y - c0.y; s += dx * dx;
        dx = xv0.z - c0.z; s += dx * dx;  dx = xv0.w - c0.w; s += dx * dx;
        dx = xv1.x - c1.x; s += dx * dx;  dx = xv1.y - c1.y; s += dx * dx;
        dx = xv1.z - c1.z; s += dx * dx;  dx = xv1.w - c1.w; s += dx * dx;
#pragma unroll
        for (int o = 16; o; o >>= 1) s += __shfl_xor_sync(0xffffffffu, s, o);
        if (s < best_s || (s == best_s && ci < best_i)) { best_s = s; best_i = ci; }
    }

    float4 c0 = __ldg(&((const float4*)cb)[(long)best_i * 64 + lane]);
    float4 c1 = __ldg(&((const float4*)cb)[(long)best_i * 64 + 32 + lane]);
    ((float4*)out_zq)[t * 64 + lane] = c0;
    ((float4*)out_zq)[t * 64 + 32 + lane] = c1;
    if (lane == 0) {
        g_part[t] = best_s;
        if (has_idx) out_idx[t] = (float)best_i;
    }
}

// ---------------- deterministic 2-stage loss reduction ----------------
__global__ void k_loss1(int per_blk) {
    __shared__ double red[256];
    int base = blockIdx.x * per_blk;
    double s = 0.0;
    for (int i = threadIdx.x; i < per_blk; i += 256) s += (double)g_part[base + i];
    red[threadIdx.x] = s;
    __syncthreads();
    for (int o = 128; o; o >>= 1) {
        if (threadIdx.x < o) red[threadIdx.x] += red[threadIdx.x + o];
        __syncthreads();
    }
    if (threadIdx.x == 0) g_lpart[blockIdx.x] = red[0];
}
__global__ void k_loss2(float* __restrict__ out_loss, int N) {
    __shared__ double red[128];
    red[threadIdx.x] = g_lpart[threadIdx.x];
    __syncthreads();
    for (int o = 64; o; o >>= 1) {
        if (threadIdx.x < o) red[threadIdx.x] += red[threadIdx.x + o];
        __syncthreads();
    }
    if (threadIdx.x == 0)
        *out_loss = (float)(1.25 * red[0] / ((double)N * DDIM));
}

// ---------------- launch ----------------
extern "C" void kernel_launch(void* const* d_in, const int* in_sizes, int n_in,
                              void* d_out, int out_size) {
    const float* z  = (const float*)d_in[0];
    const float* cb = (const float*)d_in[1];
    int N = in_sizes[0] / DDIM;
    int K = in_sizes[1] / DDIM;
    float* out = (float*)d_out;

    cudaFuncSetAttribute(k_argmin, cudaFuncAttributeMaxDynamicSharedMemorySize,
                         SMEM_TOTAL);

    k_prep_z<<<(N + 7) / 8, 256>>>(z, N);
    k_prep_c<<<(K + 7) / 8, 256>>>(cb, K);
    k_argmin<<<N / 128, 256, SMEM_TOTAL>>>(K / 128);

    long zq_elems = (long)N * DDIM;
    int has_idx  = (out_size >= zq_elems + N);
    int has_loss = (out_size >= zq_elems + N + 1);
    float* out_idx = has_idx ? (out + zq_elems) : nullptr;

    k_finish<<<(N + 7) / 8, 256>>>(z, cb, out, out_idx, has_idx, N);
    if (has_loss) {
        k_loss1<<<128, 256>>>(N / 128);
        k_loss2<<<1, 128>>>(out + zq_elems + N, N);
    }
}

// round 7
// speedup vs baseline: 2.4424x; 2.4424x over previous
#include <cuda_runtime.h>
#include <cuda_fp16.h>
#include <cstdint>

// ============================================================
// VectorQuantizer on GB300 (baseline-PTX path, no tcgen05):
//   fp16 mma.sync GEMM (16 warps, 32x32 warp tiles) +
//   per-thread top-2 -> merged top-4 + exact fp32 rescore.
//   Round 7: revert IMMA; maximize HMMA issue overlap.
// ============================================================

#define DDIM 256
#define MAXN 32768
#define MAXK 8192

__device__ __half g_zh[(size_t)MAXN * DDIM];   // fp16 tokens
__device__ __half g_ch[(size_t)MAXK * DDIM];   // fp16 codebook
__device__ float  g_cnorm[MAXK];
__device__ int    g_cand[(size_t)MAXN * 4];    // top-4 candidates per token
__device__ float  g_part[MAXN];                // per-token loss partial
__device__ double g_lpart[128];                // loss stage-1 partials

// ---------------- PTX helpers ----------------
__device__ __forceinline__ uint32_t smem_u32(const void* p) {
    uint32_t a;
    asm("{ .reg .u64 t; cvta.to.shared.u64 t, %1; cvt.u32.u64 %0, t; }" : "=r"(a) : "l"(p));
    return a;
}
__device__ __forceinline__ void cp16(uint32_t s, const void* g) {
    asm volatile("cp.async.cg.shared.global [%0], [%1], 16;" :: "r"(s), "l"(g) : "memory");
}
__device__ __forceinline__ void cp_commit() {
    asm volatile("cp.async.commit_group;" ::: "memory");
}
template <int N> __device__ __forceinline__ void cp_wait() {
    asm volatile("cp.async.wait_group %0;" :: "n"(N) : "memory");
}
__device__ __forceinline__ void ldsm4(uint32_t a[4], uint32_t addr) {
    asm volatile("ldmatrix.sync.aligned.m8n8.x4.shared.b16 {%0,%1,%2,%3}, [%4];"
                 : "=r"(a[0]), "=r"(a[1]), "=r"(a[2]), "=r"(a[3]) : "r"(addr));
}
__device__ __forceinline__ void ldsm2(uint32_t b[2], uint32_t addr) {
    asm volatile("ldmatrix.sync.aligned.m8n8.x2.shared.b16 {%0,%1}, [%2];"
                 : "=r"(b[0]), "=r"(b[1]) : "r"(addr));
}
__device__ __forceinline__ void mma16816(float d[4], const uint32_t a[4],
                                         const uint32_t b[2]) {
    asm volatile(
        "mma.sync.aligned.m16n8k16.row.col.f32.f16.f16.f32 "
        "{%0,%1,%2,%3},{%4,%5,%6,%7},{%8,%9},{%0,%1,%2,%3};"
        : "+f"(d[0]), "+f"(d[1]), "+f"(d[2]), "+f"(d[3])
        : "r"(a[0]), "r"(a[1]), "r"(a[2]), "r"(a[3]), "r"(b[0]), "r"(b[1]));
}

__device__ __forceinline__ unsigned fkey(float f) {
    unsigned u = __float_as_uint(f);
    return (u & 0x80000000u) ? ~u : (u | 0x80000000u);
}

// ---------------- SMEM map for k_argmin ----------------
// [cn: 32768][A: 128 x 528 = 67584][B: 2 x (128 x 272) = 69632]
#define AS 528                  // A row stride bytes (256 halfs + 8 pad)
#define BS 272                  // B row stride bytes (128 halfs + 8 pad)
#define CN_OFF 0
#define A_OFF 32768
#define B_OFF 100352
#define B_BYTES 34816
#define SMEM_TOTAL 169984

// ---------------- prep kernels ----------------
__global__ void k_prep_z(const float* __restrict__ z, int n4) {
    int i = blockIdx.x * blockDim.x + threadIdx.x;
    if (i >= n4) return;
    float4 v = ((const float4*)z)[i];
    __half2 a = __floats2half2_rn(v.x, v.y);
    __half2 b = __floats2half2_rn(v.z, v.w);
    uint2 o; o.x = *(uint32_t*)&a; o.y = *(uint32_t*)&b;
    ((uint2*)g_zh)[i] = o;
}

__global__ void k_prep_c(const float* __restrict__ cb, int K) {
    int warp = blockIdx.x * (blockDim.x >> 5) + (threadIdx.x >> 5);
    int lane = threadIdx.x & 31;
    if (warp >= K) return;
    float s = 0.f;
#pragma unroll
    for (int i = 0; i < 2; i++) {
        int e4 = lane + 32 * i;
        float4 v = ((const float4*)(cb + (size_t)warp * DDIM))[e4];
        s += v.x * v.x + v.y * v.y + v.z * v.z + v.w * v.w;
        __half2 a = __floats2half2_rn(v.x, v.y);
        __half2 b = __floats2half2_rn(v.z, v.w);
        uint2 o; o.x = *(uint32_t*)&a; o.y = *(uint32_t*)&b;
        ((uint2*)(g_ch + (size_t)warp * DDIM))[e4] = o;
    }
#pragma unroll
    for (int o = 16; o; o >>= 1) s += __shfl_xor_sync(0xffffffffu, s, o);
    if (lane == 0) g_cnorm[warp] = s;
}

// ---------------- fused fp16 GEMM + top-2 argmin (512 thr) ----------------
__global__ void __launch_bounds__(512, 1) k_argmin(int ntiles) {
    extern __shared__ char smem[];
    uint32_t sb = smem_u32(smem);
    int tid = threadIdx.x;
    int lane = tid & 31, wid = tid >> 5;
    int wm = wid >> 2;          // M group (0..3): rows wm*32..+32
    int wn = wid & 3;           // N group (0..3): cols wn*32..+32
    long t0 = (long)blockIdx.x * 128;

    // ---- async prologue: cn table + A panel + B chunk 0 ----
#pragma unroll
    for (int it = 0; it < 4; it++) {            // cn: 2048 x 16B
        int f = tid + 512 * it;
        cp16(sb + CN_OFF + f * 16, g_cnorm + f * 4);
    }
#pragma unroll
    for (int it = 0; it < 8; it++) {            // A: 128 rows x 32 cp16
        int f = tid + 512 * it;
        int row = f >> 5, c = f & 31;
        cp16(sb + A_OFF + row * AS + c * 16,
             g_zh + (t0 + row) * DDIM + c * 8);
    }
#pragma unroll
    for (int it = 0; it < 4; it++) {            // B chunk q=0: 128 rows x 16 cp16
        int f = tid + 512 * it;
        int row = f >> 4, c = f & 15;
        cp16(sb + B_OFF + row * BS + c * 16,
             g_ch + (size_t)row * DDIM + c * 8);
    }
    cp_commit();

    // ---- state ----
    float d[2][4][4];
    float ts[4][2];
    int   ti[4][2];
#pragma unroll
    for (int s = 0; s < 4; s++)
#pragma unroll
        for (int e = 0; e < 2; e++) { ts[s][e] = 3.4e38f; ti[s][e] = 0; }

    int a_r = (lane & 7) + ((lane >> 3) & 1) * 8;
    int a_k = ((lane >> 4) & 1) * 8;
    int b_r = lane & 7;
    int b_k = ((lane >> 3) & 1) * 8;

    int Q = ntiles * 2;                          // 128-dim chunks
    for (int q = 0; q < Q; q++) {
        int buf = q & 1;
        if (q + 1 < Q) {
            int nq = q + 1;
            int nkt = nq >> 1, ndc = nq & 1;
            uint32_t bb = sb + B_OFF + (nq & 1) * B_BYTES;
#pragma unroll
            for (int it = 0; it < 4; it++) {
                int f = tid + 512 * it;
                int row = f >> 4, c = f & 15;
                cp16(bb + row * BS + c * 16,
                     g_ch + ((size_t)(nkt * 128 + row)) * DDIM + ndc * 128 + c * 8);
            }
            cp_commit();
            cp_wait<1>();
        } else {
            cp_wait<0>();
        }
        __syncthreads();

        int kt = q >> 1, dc = q & 1;
        if (dc == 0) {
#pragma unroll
            for (int mi = 0; mi < 2; mi++)
#pragma unroll
                for (int ni = 0; ni < 4; ni++)
#pragma unroll
                    for (int r = 0; r < 4; r++) d[mi][ni][r] = 0.f;
        }
        uint32_t Bb = sb + B_OFF + buf * B_BYTES;

#pragma unroll
        for (int k0 = 0; k0 < 128; k0 += 16) {
            uint32_t a[2][4], bf[4][2];
#pragma unroll
            for (int mi = 0; mi < 2; mi++)
                ldsm4(a[mi], sb + A_OFF + (wm * 32 + mi * 16 + a_r) * AS +
                             (dc * 128 + k0 + a_k) * 2);
#pragma unroll
            for (int ni = 0; ni < 4; ni++)
                ldsm2(bf[ni], Bb + (wn * 32 + ni * 8 + b_r) * BS + (k0 + b_k) * 2);
#pragma unroll
            for (int mi = 0; mi < 2; mi++)
#pragma unroll
                for (int ni = 0; ni < 4; ni++)
                    mma16816(d[mi][ni], a[mi], bf[ni]);
        }

        if (dc == 1) {
            // ---- scoring: s = cn - 2*dot, per-slot min, top-2 ----
            int cbase = kt * 128 + wn * 32 + 2 * (lane & 3);
            float2 cn2[4];
#pragma unroll
            for (int ni = 0; ni < 4; ni++)
                cn2[ni] = *(const float2*)(smem + CN_OFF + (cbase + ni * 8) * 4);
#pragma unroll
            for (int mi = 0; mi < 2; mi++)
#pragma unroll
                for (int h = 0; h < 2; h++) {
                    int slot = mi * 2 + h;
                    float bs = 3.4e38f; int bc = 0;
#pragma unroll
                    for (int ni = 0; ni < 4; ni++) {
                        float s0 = fmaf(-2.f, d[mi][ni][h * 2 + 0], cn2[ni].x);
                        float s1 = fmaf(-2.f, d[mi][ni][h * 2 + 1], cn2[ni].y);
                        int c0 = cbase + ni * 8, c1 = c0 + 1;
                        if (s0 < bs) { bs = s0; bc = c0; }
                        if (s1 < bs) { bs = s1; bc = c1; }
                    }
                    if (bs < ts[slot][1]) {
                        if (bs < ts[slot][0]) {
                            ts[slot][1] = ts[slot][0]; ti[slot][1] = ti[slot][0];
                            ts[slot][0] = bs; ti[slot][0] = bc;
                        } else { ts[slot][1] = bs; ti[slot][1] = bc; }
                    }
                }
        }
        __syncthreads();
    }

    // ---- merge 16 contributors x 2 entries per token -> top-4 ----
    unsigned long long* red = (unsigned long long*)smem;
    int contrib = wn * 4 + (lane & 3);
#pragma unroll
    for (int mi = 0; mi < 2; mi++)
#pragma unroll
        for (int h = 0; h < 2; h++) {
            int slot = mi * 2 + h;
            int token = wm * 32 + mi * 16 + h * 8 + (lane >> 2);
#pragma unroll
            for (int e = 0; e < 2; e++)
                red[token * 32 + contrib * 2 + e] =
                    (((unsigned long long)fkey(ts[slot][e])) << 32) |
                    (unsigned)ti[slot][e];
        }
    __syncthreads();

    if (tid < 128) {
        unsigned long long b1 = ~0ull, b2 = ~0ull, b3 = ~0ull, b4 = ~0ull;
#pragma unroll 4
        for (int j = 0; j < 32; j++) {
            unsigned long long v = red[tid * 32 + j];
            if (v < b4) {
                if (v < b3) {
                    b4 = b3;
                    if (v < b2) { b3 = b2; if (v < b1) { b2 = b1; b1 = v; } else b2 = v; }
                    else b3 = v;
                } else b4 = v;
            }
        }
        long t = t0 + tid;
        g_cand[t * 4 + 0] = (int)(b1 & 0xffffffffu);
        g_cand[t * 4 + 1] = (int)(b2 & 0xffffffffu);
        g_cand[t * 4 + 2] = (int)(b3 & 0xffffffffu);
        g_cand[t * 4 + 3] = (int)(b4 & 0xffffffffu);
    }
}

// ---------------- exact rescore + gather + loss partial ----------------
__global__ void k_finish(const float* __restrict__ z, const float* __restrict__ cb,
                         float* __restrict__ out_zq, float* __restrict__ out_idx,
                         int has_idx, int N) {
    int warp = blockIdx.x * (blockDim.x >> 5) + (threadIdx.x >> 5);
    int lane = threadIdx.x & 31;
    if (warp >= N) return;
    long t = warp;

    float4 xv0 = ((const float4*)z)[t * 64 + lane];
    float4 xv1 = ((const float4*)z)[t * 64 + 32 + lane];

    float best_s = 3.4e38f;
    int best_i = 0x7fffffff;
#pragma unroll
    for (int r = 0; r < 4; r++) {
        int ci = g_cand[t * 4 + r];
        float4 c0 = __ldg(&((const float4*)cb)[(long)ci * 64 + lane]);
        float4 c1 = __ldg(&((const float4*)cb)[(long)ci * 64 + 32 + lane]);
        float dx, s = 0.f;
        dx = xv0.x - c0.x; s += dx * dx;  dx = xv0.y - c0.y; s += dx * dx;
        dx = xv0.z - c0.z; s += dx * dx;  dx = xv0.w - c0.w; s += dx * dx;
        dx = xv1.x - c1.x; s += dx * dx;  dx = xv1.y - c1.y; s += dx * dx;
        dx = xv1.z - c1.z; s += dx * dx;  dx = xv1.w - c1.w; s += dx * dx;
#pragma unroll
        for (int o = 16; o; o >>= 1) s += __shfl_xor_sync(0xffffffffu, s, o);
        if (s < best_s || (s == best_s && ci < best_i)) { best_s = s; best_i = ci; }
    }
    float4 c0 = __ldg(&((const float4*)cb)[(long)best_i * 64 + lane]);
    float4 c1 = __ldg(&((const float4*)cb)[(long)best_i * 64 + 32 + lane]);
    ((float4*)out_zq)[t * 64 + lane] = c0;
    ((float4*)out_zq)[t * 64 + 32 + lane] = c1;
    if (lane == 0) {
        g_part[t] = best_s;
        if (has_idx) out_idx[t] = (float)best_i;
    }
}

// ---------------- deterministic 2-stage loss reduction ----------------
__global__ void k_loss1(int per_blk) {
    __shared__ double red[256];
    int base = blockIdx.x * per_blk;
    double s = 0.0;
    for (int i = threadIdx.x; i < per_blk; i += 256) s += (double)g_part[base + i];
    red[threadIdx.x] = s;
    __syncthreads();
    for (int o = 128; o; o >>= 1) {
        if (threadIdx.x < o) red[threadIdx.x] += red[threadIdx.x + o];
        __syncthreads();
    }
    if (threadIdx.x == 0) g_lpart[blockIdx.x] = red[0];
}
__global__ void k_loss2(float* __restrict__ out_loss, int N) {
    __shared__ double red[128];
    red[threadIdx.x] = g_lpart[threadIdx.x];
    __syncthreads();
    for (int o = 64; o; o >>= 1) {
        if (threadIdx.x < o) red[threadIdx.x] += red[threadIdx.x + o];
        __syncthreads();
    }
    if (threadIdx.x == 0)
        *out_loss = (float)(1.25 * red[0] / ((double)N * DDIM));
}

// ---------------- launch ----------------
extern "C" void kernel_launch(void* const* d_in, const int* in_sizes, int n_in,
                              void* d_out, int out_size) {
    const float* z  = (const float*)d_in[0];
    const float* cb = (const float*)d_in[1];
    int N = in_sizes[0] / DDIM;
    int K = in_sizes[1] / DDIM;
    float* out = (float*)d_out;

    cudaFuncSetAttribute(k_argmin, cudaFuncAttributeMaxDynamicSharedMemorySize,
                         SMEM_TOTAL);

    int n4 = N * (DDIM / 4);
    k_prep_z<<<(n4 + 255) / 256, 256>>>(z, n4);
    k_prep_c<<<(K + 7) / 8, 256>>>(cb, K);
    k_argmin<<<N / 128, 512, SMEM_TOTAL>>>(K / 128);

    long zq_elems = (long)N * DDIM;
    int has_idx  = (out_size >= zq_elems + N);
    int has_loss = (out_size >= zq_elems + N + 1);
    float* out_idx = has_idx ? (out + zq_elems) : nullptr;

    k_finish<<<(N + 7) / 8, 256>>>(z, cb, out, out_idx, has_idx, N);
    if (has_loss) {
        k_loss1<<<128, 256>>>(N / 128);
        k_loss2<<<1, 128>>>(out + zq_elems + N, N);
    }
}